// round 6
// baseline (speedup 1.0000x reference)
#include <cuda_runtime.h>

// AdvectionDiffusionReaction2M — temporal-blocked stencil, 2x4-cells-per-thread,
// 352-block grid. 199 steps = 24 chunks of 8 + 1 chunk of 7.
// Block (16,16); thread owns 2 rows x 4 cols of a 32x64 extended tile; block
// owns central 16x48. Vertical neighbor rows via 128-bit smem exchange (1 sync
// per level), horizontal pack edges via shuffle. Level loop fully unrolled.
// Rim garbage propagates 1 cell/level; owned core margin = S = 8.
// ROUND-5 BUGFIX: store predicate was missing the tx upper bound (tx < 14),
// letting halo threads stomp the neighboring block's owned columns.

#define NN     512
#define N2     (NN * NN)
#define S      8
#define EXTW   64
#define EXTH   32
#define OWNW   48
#define OWNH   16
#define NSTEPS 199

template <int NS>
__global__ __launch_bounds__(256)
void adr_chunk_kernel(const float* __restrict__ src,
                      float*       __restrict__ out,
                      int t0,
                      const float* __restrict__ k1p,
                      const float* __restrict__ k2p,
                      const float* __restrict__ a1p,
                      const float* __restrict__ a2p)
{
    // double-buffered boundary-row exchange; thread row ty+1, pads at 0 / 17
    __shared__ float s_top[2][18][EXTW];
    __shared__ float s_bot[2][18][EXTW];

    const int tx = threadIdx.x;   // 0..15, cols 4tx..4tx+3 of ext tile
    const int ty = threadIdx.y;   // 0..15, rows 2ty..2ty+1

    const int ro0 = blockIdx.y * OWNH;   // by: 0..31
    const int co0 = blockIdx.x * OWNW;   // bx: 0..10
    const int gi0 = ro0 - S + 2 * ty;
    const int gj0 = co0 - S + 4 * tx;

    const float k1 = __ldg(k1p), k2 = __ldg(k2p);
    const float a1 = __ldg(a1p), a2 = __ldg(a2p);
    const float inv_ksum = 1.0f / (k1 + k2);

    const float dx2f   = (float)((1.0 / 511.0) * (1.0 / 511.0));
    const float twodxf = (float)(2.0 / 511.0);
    const float DT     = 1e-7f;

    // 4-col packs never straddle j=256 (256 - (co0-S) is a multiple of 4)
    const float kap  = (gj0 < 256) ? k1 : k2;
    const float al   = (gj0 < 256) ? a1 : a2;
    const float c_al = DT * al / dx2f;
    const float cx   = DT * kap / twodxf;
    const float ck   = DT * kap;

    // ---- clamped initial load (field at step t0-1) ----
    float v[2][4];
    #pragma unroll
    for (int r = 0; r < 2; ++r) {
        const int gi = min(max(gi0 + r, 0), NN - 1);
        #pragma unroll
        for (int c = 0; c < 4; ++c) {
            const int gj = min(max(gj0 + c, 0), NN - 1);
            v[r][c] = src[gi * NN + gj];
        }
    }

    // intra-thread fixup / ownership flags
    const bool ifc    = (gj0 + 3 == 255);                       // bx==5, tx==5
    const bool fix_rt = (blockIdx.y == 0  && ty == 4);          // row 0   <- row 1  : n[0]<-n[1]
    const bool fix_rb = (ro0 == NN - OWNH && ty == 11);         // row 511 <- row 510: n[1]<-n[0]
    const bool fix_cl = (blockIdx.x == 0  && tx == 2);          // col 0   <- col 1  : c0<-c1
    const bool fix_cr = (co0 == 480       && tx == 9);          // col 511 <- col 510: c3<-c2
    const bool store_ok = (ty >= 4 && ty < 12) &&
                          (tx >= 2 && tx < 14) &&               // <- restored upper bound
                          (gj0 < NN);

    float* __restrict__ slab = out + (size_t)t0 * N2;
    const unsigned FULL = 0xffffffffu;

    #pragma unroll
    for (int k = 0; k < NS; ++k) {
        const int pb = k & 1;

        // ---- vertical boundary exchange (old values) ----
        *(float4*)&s_top[pb][ty + 1][4 * tx] = make_float4(v[0][0], v[0][1], v[0][2], v[0][3]);
        *(float4*)&s_bot[pb][ty + 1][4 * tx] = make_float4(v[1][0], v[1][1], v[1][2], v[1][3]);
        __syncthreads();
        const float4 upv = *(const float4*)&s_bot[pb][ty][4 * tx];       // row above
        const float4 dnv = *(const float4*)&s_top[pb][ty + 2][4 * tx];   // row below
        const float up[4] = {upv.x, upv.y, upv.z, upv.w};
        const float dn[4] = {dnv.x, dnv.y, dnv.z, dnv.w};

        // ---- horizontal pack edges (old values) ----
        float lft[2], rgt[2];
        #pragma unroll
        for (int r = 0; r < 2; ++r) {
            lft[r] = __shfl_up_sync(FULL,   v[r][3], 1);
            rgt[r] = __shfl_down_sync(FULL, v[r][0], 1);
        }

        // ---- 8 cell updates ----
        float n[2][4];
        #pragma unroll
        for (int r = 0; r < 2; ++r) {
            #pragma unroll
            for (int c = 0; c < 4; ++c) {
                const float cu = v[r][c];
                const float u_ = (r == 0) ? up[c] : v[0][c];
                const float d_ = (r == 1) ? dn[c] : v[1][c];
                const float l_ = (c == 0) ? lft[r] : v[r][c - 1];
                const float r_ = (c == 3) ? rgt[r] : v[r][c + 1];

                const float sum  = (u_ + d_) + (l_ + r_);
                const float lap  = fmaf(-4.0f, cu, sum);
                const float A    = fmaf(cu, d_ - u_, l_ - r_);
                const float adv  = cu * A;
                const float q    = fmaf(cu, cu, -cu);
                const float reac = cu * (q + 1.0f);

                float val = fmaf(c_al, lap, cu);
                val = fmaf(-cx, adv, val);
                val = fmaf(ck, reac, val);
                n[r][c] = val;
            }
        }

        // ---- interface column j=255: value from OLD neighbors (254, 256) ----
        if (ifc) {
            n[0][3] = (k1 * rgt[0] + k2 * v[0][2]) * inv_ksum;
            n[1][3] = (k1 * rgt[1] + k2 * v[1][2]) * inv_ksum;
        }

        // ---- domain-edge fixups (rows then cols, matching reference order) ----
        if (fix_rt) { n[0][0] = n[1][0]; n[0][1] = n[1][1]; n[0][2] = n[1][2]; n[0][3] = n[1][3]; }
        if (fix_rb) { n[1][0] = n[0][0]; n[1][1] = n[0][1]; n[1][2] = n[0][2]; n[1][3] = n[0][3]; }
        if (fix_cl) { n[0][0] = n[0][1]; n[1][0] = n[1][1]; }
        if (fix_cr) { n[0][3] = n[0][2]; n[1][3] = n[1][2]; }

        // ---- store owned 2x4 pack (coalesced 16B stores) ----
        if (store_ok) {
            *(float4*)&slab[(size_t)(gi0    ) * NN + gj0] = make_float4(n[0][0], n[0][1], n[0][2], n[0][3]);
            *(float4*)&slab[(size_t)(gi0 + 1) * NN + gj0] = make_float4(n[1][0], n[1][1], n[1][2], n[1][3]);
        }

        slab += N2;
        #pragma unroll
        for (int r = 0; r < 2; ++r)
            #pragma unroll
            for (int c = 0; c < 4; ++c)
                v[r][c] = n[r][c];
    }
}

extern "C" void kernel_launch(void* const* d_in, const int* in_sizes, int n_in,
                              void* d_out, int out_size)
{
    const float* u0  = (const float*)d_in[0];
    const float* k1p = (const float*)d_in[1];
    const float* k2p = (const float*)d_in[2];
    const float* a1p = (const float*)d_in[3];
    const float* a2p = (const float*)d_in[4];
    float* out = (float*)d_out;

    dim3 block(16, 16, 1);
    dim3 grid((NN + OWNW - 1) / OWNW, NN / OWNH, 1);   // 11 x 32 = 352 blocks

    int t0 = 0;
    for (int c = 0; c < 24; ++c) {
        const float* src = (t0 == 0) ? u0 : (out + (size_t)(t0 - 1) * N2);
        adr_chunk_kernel<8><<<grid, block>>>(src, out, t0, k1p, k2p, a1p, a2p);
        t0 += 8;
    }
    {
        const float* src = out + (size_t)(t0 - 1) * N2;
        adr_chunk_kernel<7><<<grid, block>>>(src, out, t0, k1p, k2p, a1p, a2p);
    }
}

// round 7
// speedup vs baseline: 1.2802x; 1.2802x over previous
#include <cuda_runtime.h>

// AdvectionDiffusionReaction2M — temporal-blocked stencil, round-4 geometry
// (4x4 cells/thread, 48x48 owned, 64x64 extended, 121 blocks, S=8, 25 launches)
// with packed f32x2 arithmetic (Blackwell FFMA2 path via inline PTX).
// Round-6 lesson: total instruction volume is the binding constraint; this
// halves the FMA-pipe op count per cell instead of reshaping the tiling.

#define NN     512
#define N2     (NN * NN)
#define S      8
#define TILEW  48
#define EXT    64
#define NSTEPS 199

typedef unsigned long long u64;

__device__ __forceinline__ u64 pack2(float lo, float hi) {
    u64 d;
    asm("mov.b64 %0, {%1, %2};" : "=l"(d) : "r"(__float_as_uint(lo)), "r"(__float_as_uint(hi)));
    return d;
}
__device__ __forceinline__ void unpack2(float& lo, float& hi, u64 v) {
    unsigned a, b;
    asm("mov.b64 {%0, %1}, %2;" : "=r"(a), "=r"(b) : "l"(v));
    lo = __uint_as_float(a); hi = __uint_as_float(b);
}
__device__ __forceinline__ u64 fma2(u64 a, u64 b, u64 c) {
    u64 d; asm("fma.rn.f32x2 %0, %1, %2, %3;" : "=l"(d) : "l"(a), "l"(b), "l"(c)); return d;
}
__device__ __forceinline__ u64 add2(u64 a, u64 b) {
    u64 d; asm("add.rn.f32x2 %0, %1, %2;" : "=l"(d) : "l"(a), "l"(b)); return d;
}
__device__ __forceinline__ u64 mul2(u64 a, u64 b) {
    u64 d; asm("mul.rn.f32x2 %0, %1, %2;" : "=l"(d) : "l"(a), "l"(b)); return d;
}

template <int NS>
__global__ __launch_bounds__(256)
void adr_chunk_kernel(const float* __restrict__ src,
                      float*       __restrict__ out,
                      int t0,
                      const float* __restrict__ k1p,
                      const float* __restrict__ k2p,
                      const float* __restrict__ a1p,
                      const float* __restrict__ a2p)
{
    // double-buffered strip-boundary rows (packs); thread row ty+1, pads 0/17
    __shared__ u64 s_top[2][18][EXT / 2];
    __shared__ u64 s_bot[2][18][EXT / 2];

    const int tx = threadIdx.x;   // 0..15, cols 4tx..4tx+3 of ext tile
    const int ty = threadIdx.y;   // 0..15, rows 4ty..4ty+3

    const int ro0 = blockIdx.y * TILEW;
    const int co0 = blockIdx.x * TILEW;
    const int gi0 = ro0 - S + 4 * ty;
    const int gj0 = co0 - S + 4 * tx;

    const float k1 = __ldg(k1p), k2 = __ldg(k2p);
    const float a1 = __ldg(a1p), a2 = __ldg(a2p);
    const float inv_ksum = 1.0f / (k1 + k2);

    const float dx2f   = (float)((1.0 / 511.0) * (1.0 / 511.0));
    const float twodxf = (float)(2.0 / 511.0);
    const float DT     = 1e-7f;

    // 4-col packs never straddle j=256
    const float kap  = (gj0 < 256) ? k1 : k2;
    const float al   = (gj0 < 256) ? a1 : a2;
    const u64 c_al2 = pack2(DT * al / dx2f,   DT * al / dx2f);
    const u64 ncx2  = pack2(-DT * kap / twodxf, -DT * kap / twodxf);
    const u64 ck2   = pack2(DT * kap, DT * kap);
    const u64 NEG1  = pack2(-1.0f, -1.0f);
    const u64 M4    = pack2(-4.0f, -4.0f);
    const u64 ONE   = pack2(1.0f, 1.0f);

    // sub2(a,b) = a - b, exact: b*(-1)+a
    #define SUB2(a, b) fma2((b), NEG1, (a))

    // ---- clamped initial load, then pack: va[r]=(c0,c1), vb[r]=(c2,c3) ----
    u64 va[4], vb[4];
    #pragma unroll
    for (int r = 0; r < 4; ++r) {
        const int gi = min(max(gi0 + r, 0), NN - 1);
        float t[4];
        #pragma unroll
        for (int c = 0; c < 4; ++c) {
            const int gj = min(max(gj0 + c, 0), NN - 1);
            t[c] = src[gi * NN + gj];
        }
        va[r] = pack2(t[0], t[1]);
        vb[r] = pack2(t[2], t[3]);
    }

    // intra-thread flags (validated round 4)
    const bool ifc      = (gj0 + 3 == 255);
    const bool fix_rt   = (blockIdx.y == 0  && ty == 2);   // row 0   <- row 1
    const bool fix_rb   = (ro0 == 480       && ty == 9);   // row 511 <- row 510
    const bool fix_cl   = (blockIdx.x == 0  && tx == 2);   // col 0   <- col 1
    const bool fix_cr   = (co0 == 480       && tx == 9);   // col 511 <- col 510
    const bool store_ok = (tx >= 2 && tx < 14 && ty >= 2 && ty < 14 &&
                           gi0 < NN && gj0 < NN);

    float* __restrict__ slab = out + (size_t)t0 * N2;
    const unsigned FULL = 0xffffffffu;

    #pragma unroll
    for (int k = 0; k < NS; ++k) {
        const int pb = k & 1;

        // ---- vertical boundary exchange (old packs) ----
        s_top[pb][ty + 1][2 * tx]     = va[0];
        s_top[pb][ty + 1][2 * tx + 1] = vb[0];
        s_bot[pb][ty + 1][2 * tx]     = va[3];
        s_bot[pb][ty + 1][2 * tx + 1] = vb[3];
        __syncthreads();
        const u64 up_a = s_bot[pb][ty][2 * tx];
        const u64 up_b = s_bot[pb][ty][2 * tx + 1];
        const u64 dn_a = s_top[pb][ty + 2][2 * tx];
        const u64 dn_b = s_top[pb][ty + 2][2 * tx + 1];

        u64 na[4], nb[4];
        float oc2[4], rgt_s[4];   // old c2 and right-shfl scalar, kept for interface fixup

        #pragma unroll
        for (int r = 0; r < 4; ++r) {
            float c0, c1, c2, c3;
            unpack2(c0, c1, va[r]);
            unpack2(c2, c3, vb[r]);
            const float lft = __shfl_up_sync(FULL,   c3, 1);
            const float rgt = __shfl_down_sync(FULL, c0, 1);
            oc2[r] = c2; rgt_s[r] = rgt;

            const u64 La = pack2(lft, c0);   // left neighbors of pack a
            const u64 Mi = pack2(c1, c2);    // right of a == left of b
            const u64 Rb = pack2(c3, rgt);   // right neighbors of pack b

            const u64 u_a = (r == 0) ? up_a : va[r - 1];
            const u64 u_b = (r == 0) ? up_b : vb[r - 1];
            const u64 d_a = (r == 3) ? dn_a : va[r + 1];
            const u64 d_b = (r == 3) ? dn_b : vb[r + 1];

            #pragma unroll
            for (int h = 0; h < 2; ++h) {
                const u64 cu = h ? vb[r] : va[r];
                const u64 u_ = h ? u_b   : u_a;
                const u64 d_ = h ? d_b   : d_a;
                const u64 l_ = h ? Mi    : La;
                const u64 r_ = h ? Rb    : Mi;

                const u64 sum  = add2(add2(u_, d_), add2(l_, r_));
                const u64 lap  = fma2(M4, cu, sum);
                const u64 A    = fma2(cu, SUB2(d_, u_), SUB2(l_, r_));
                const u64 adv  = mul2(cu, A);
                const u64 t    = SUB2(cu, ONE);            // c - 1
                const u64 t2   = fma2(cu, t, ONE);         // c(c-1) + 1
                const u64 reac = mul2(cu, t2);             // c^3 - c^2 + c

                u64 val = fma2(c_al2, lap, cu);
                val = fma2(ncx2, adv, val);
                val = fma2(ck2, reac, val);
                if (h) nb[r] = val; else na[r] = val;
            }
        }

        // ---- interface column j=255 (pack b hi), from OLD neighbors ----
        if (ifc) {
            #pragma unroll
            for (int r = 0; r < 4; ++r) {
                float lo, hi;
                unpack2(lo, hi, nb[r]);
                hi = (k1 * rgt_s[r] + k2 * oc2[r]) * inv_ksum;
                nb[r] = pack2(lo, hi);
            }
        }

        // ---- domain-edge fixups (rows then cols) ----
        if (fix_rt) { na[0] = na[1]; nb[0] = nb[1]; }
        if (fix_rb) { na[3] = na[2]; nb[3] = nb[2]; }
        if (fix_cl) {
            #pragma unroll
            for (int r = 0; r < 4; ++r) { float lo, hi; unpack2(lo, hi, na[r]); na[r] = pack2(hi, hi); }
        }
        if (fix_cr) {
            #pragma unroll
            for (int r = 0; r < 4; ++r) { float lo, hi; unpack2(lo, hi, nb[r]); nb[r] = pack2(lo, lo); }
        }

        // ---- store owned 4x4 (coalesced 16B stores) ----
        if (store_ok) {
            #pragma unroll
            for (int r = 0; r < 4; ++r) {
                float x0, x1, x2, x3;
                unpack2(x0, x1, na[r]);
                unpack2(x2, x3, nb[r]);
                *(float4*)&slab[(size_t)(gi0 + r) * NN + gj0] = make_float4(x0, x1, x2, x3);
            }
        }

        slab += N2;
        #pragma unroll
        for (int r = 0; r < 4; ++r) { va[r] = na[r]; vb[r] = nb[r]; }
    }
    #undef SUB2
}

extern "C" void kernel_launch(void* const* d_in, const int* in_sizes, int n_in,
                              void* d_out, int out_size)
{
    const float* u0  = (const float*)d_in[0];
    const float* k1p = (const float*)d_in[1];
    const float* k2p = (const float*)d_in[2];
    const float* a1p = (const float*)d_in[3];
    const float* a2p = (const float*)d_in[4];
    float* out = (float*)d_out;

    dim3 block(16, 16, 1);
    dim3 grid((NN + TILEW - 1) / TILEW, (NN + TILEW - 1) / TILEW, 1);  // 11 x 11

    int t0 = 0;
    for (int c = 0; c < 24; ++c) {
        const float* src = (t0 == 0) ? u0 : (out + (size_t)(t0 - 1) * N2);
        adr_chunk_kernel<8><<<grid, block>>>(src, out, t0, k1p, k2p, a1p, a2p);
        t0 += 8;
    }
    {
        const float* src = out + (size_t)(t0 - 1) * N2;
        adr_chunk_kernel<7><<<grid, block>>>(src, out, t0, k1p, k2p, a1p, a2p);
    }
}